// round 10
// baseline (speedup 1.0000x reference)
#include <cuda_runtime.h>
#include <cuda_bf16.h>
#include <math.h>

#define BATCH 16
#define SEQ   3136
#define CDIM  512
#define C3    1536
#define NHEAD 8
#define HD    64
#define AG    49
#define HW    56
#define ASCALE 0.125f

// ---------------- device-global scratch (no allocation allowed) ----------------
__device__ float g_qkv[BATCH * SEQ * C3];          // (b, n, 3c)
__device__ float g_agent[BATCH * AG * CDIM];       // (b, 49, c)
__device__ float g_av[BATCH * NHEAD * AG * HD];    // agent_v
__device__ float g_pb[NHEAD * AG * SEQ];           // stage-1 bias (upsampled)
__device__ float g_ab[NHEAD * SEQ * AG];           // stage-2 bias (upsampled)
__device__ float g_t[BATCH * SEQ * CDIM];          // attn out (pre-dwc, pre-proj)

// bf16 hi/lo split operands for tensor-core GEMMs
__device__ __nv_bfloat16 g_xhi[BATCH * SEQ * CDIM];
__device__ __nv_bfloat16 g_xlo[BATCH * SEQ * CDIM];
__device__ __nv_bfloat16 g_thi[BATCH * SEQ * CDIM];
__device__ __nv_bfloat16 g_tlo[BATCH * SEQ * CDIM];
__device__ __nv_bfloat16 g_wqhi[C3 * CDIM];
__device__ __nv_bfloat16 g_wqlo[C3 * CDIM];
__device__ __nv_bfloat16 g_wphi[CDIM * CDIM];
__device__ __nv_bfloat16 g_wplo[CDIM * CDIM];

// ---------------- fp32 -> bf16 hi/lo split (vectorized) ------------------------
__global__ void split_kernel(const float* __restrict__ in,
                             __nv_bfloat16* __restrict__ hi,
                             __nv_bfloat16* __restrict__ lo, int n4)
{
    int i = blockIdx.x * blockDim.x + threadIdx.x;
    if (i >= n4) return;
    float4 v = ((const float4*)in)[i];
    __nv_bfloat16 h0 = __float2bfloat16(v.x);
    __nv_bfloat16 h1 = __float2bfloat16(v.y);
    __nv_bfloat16 h2 = __float2bfloat16(v.z);
    __nv_bfloat16 h3 = __float2bfloat16(v.w);
    __nv_bfloat16 l0 = __float2bfloat16(v.x - __bfloat162float(h0));
    __nv_bfloat16 l1 = __float2bfloat16(v.y - __bfloat162float(h1));
    __nv_bfloat16 l2 = __float2bfloat16(v.z - __bfloat162float(h2));
    __nv_bfloat16 l3 = __float2bfloat16(v.w - __bfloat162float(h3));
    ((__nv_bfloat162*)hi)[2 * i]     = __nv_bfloat162(h0, h1);
    ((__nv_bfloat162*)hi)[2 * i + 1] = __nv_bfloat162(h2, h3);
    ((__nv_bfloat162*)lo)[2 * i]     = __nv_bfloat162(l0, l1);
    ((__nv_bfloat162*)lo)[2 * i + 1] = __nv_bfloat162(l2, l3);
}

// ---------------- tensor-core GEMM:  C[M,N] = A[M,K] * B[N,K]^T (+bias) --------
// 2-term bf16 split, 3 MMAs (hh, hl, lh). BM=BN=128, BK=16, 3-stage cp.async.
// 256 threads, 2 CTAs/SM, warp tile 64x32 via mma.m16n8k16. K multiple of 16.
#define MMA_OP(D, A, B)                                                          \
    asm volatile("mma.sync.aligned.m16n8k16.row.col.f32.bf16.bf16.f32 "          \
                 "{%0,%1,%2,%3}, {%4,%5,%6,%7}, {%8,%9}, {%0,%1,%2,%3};\n"       \
                 : "+f"(D[0]), "+f"(D[1]), "+f"(D[2]), "+f"(D[3])                \
                 : "r"(A[0]), "r"(A[1]), "r"(A[2]), "r"(A[3]),                   \
                   "r"(B[0]), "r"(B[1]))

#define LDSM4(R, ADDR)                                                           \
    asm volatile("ldmatrix.sync.aligned.m8n8.x4.shared.b16 {%0,%1,%2,%3}, [%4];\n" \
                 : "=r"(R[0]), "=r"(R[1]), "=r"(R[2]), "=r"(R[3]) : "r"(ADDR))

#define CPA16(DST, SRC)                                                          \
    asm volatile("cp.async.ca.shared.global [%0], [%1], 16;\n"                   \
                 :: "r"(DST), "l"(SRC))

// stage row = 64B = 4 chunks of 16B: chunks 0-1 = hi k0-15, chunks 2-3 = lo.
// physical chunk = logical ^ ((row>>1)&3)  (conflict-free for ldmatrix)
__device__ __forceinline__ unsigned swz64(unsigned base, int row, int chunk)
{
    return base + row * 64 + ((chunk ^ ((row >> 1) & 3)) << 4);
}

__global__ __launch_bounds__(256, 2) void gemm_bf16x3_nt(
    const __nv_bfloat16* __restrict__ Ahi, const __nv_bfloat16* __restrict__ Alo,
    const __nv_bfloat16* __restrict__ Bhi, const __nv_bfloat16* __restrict__ Blo,
    float* __restrict__ C, const float* __restrict__ bias,
    int M, int N, int K)
{
    __shared__ __align__(1024) unsigned char sA[3 * 128 * 64];
    __shared__ __align__(1024) unsigned char sB[3 * 128 * 64];
    const int tid = threadIdx.x;
    const int lane = tid & 31;
    const int wm = (tid >> 5) >> 2;       // 0-1
    const int wn = (tid >> 5) & 3;        // 0-3
    const int bm = blockIdx.y * 128, bn = blockIdx.x * 128;

    const unsigned sAb = (unsigned)__cvta_generic_to_shared(sA);
    const unsigned sBb = (unsigned)__cvta_generic_to_shared(sB);

    // loader mapping: 2 threads per row, each does one 16B hi + one 16B lo chunk
    const int lr = tid >> 1;              // 0..127
    const int lc = tid & 1;               // chunk 0/1 (hi), +2 (lo)
    const __nv_bfloat16* gAh = Ahi + (size_t)(bm + lr) * K + lc * 8;
    const __nv_bfloat16* gAl = Alo + (size_t)(bm + lr) * K + lc * 8;
    const __nv_bfloat16* gBh = Bhi + (size_t)(bn + lr) * K + lc * 8;
    const __nv_bfloat16* gBl = Blo + (size_t)(bn + lr) * K + lc * 8;
    const unsigned swzh = (unsigned)((lc       ^ ((lr >> 1) & 3)) << 4);
    const unsigned swzl = (unsigned)(((lc + 2) ^ ((lr >> 1) & 3)) << 4);

#define ISSUE_STAGE(st, k0)                                                \
    do {                                                                   \
        unsigned a0 = sAb + (st) * 8192 + lr * 64;                         \
        unsigned b0 = sBb + (st) * 8192 + lr * 64;                         \
        CPA16(a0 + swzh, gAh + (k0));                                      \
        CPA16(a0 + swzl, gAl + (k0));                                      \
        CPA16(b0 + swzh, gBh + (k0));                                      \
        CPA16(b0 + swzl, gBl + (k0));                                      \
    } while (0)

    float acc[4][4][4];
#pragma unroll
    for (int i = 0; i < 4; i++)
#pragma unroll
        for (int j = 0; j < 4; j++)
#pragma unroll
            for (int k = 0; k < 4; k++) acc[i][j][k] = 0.f;

    const int iters = K >> 4;
    ISSUE_STAGE(0, 0);
    asm volatile("cp.async.commit_group;\n" ::);
    ISSUE_STAGE(1, 16);
    asm volatile("cp.async.commit_group;\n" ::);

    for (int it = 0; it < iters; ++it) {
        asm volatile("cp.async.wait_group 1;\n" ::);
        __syncthreads();
        if (it + 2 < iters) {
            int st = (it + 2) % 3;
            int k0 = (it + 2) << 4;
            ISSUE_STAGE(st, k0);
        }
        asm volatile("cp.async.commit_group;\n" ::);

        const unsigned baseA = sAb + (it % 3) * 8192;
        const unsigned baseB = sBb + (it % 3) * 8192;

        // B fragments: 8 n-tiles' worth in 16 regs
        unsigned bh[4][2], bl[4][2];
        const int m8 = lane >> 3;
#pragma unroll
        for (int nt2 = 0; nt2 < 2; ++nt2) {
            int row = wn * 32 + nt2 * 16 + (lane & 7) + ((m8 >> 1) << 3);
            unsigned q[4], p[4];
            LDSM4(q, swz64(baseB, row, m8 & 1));
            LDSM4(p, swz64(baseB, row, 2 + (m8 & 1)));
            bh[nt2 * 2][0] = q[0]; bh[nt2 * 2][1] = q[1];
            bh[nt2 * 2 + 1][0] = q[2]; bh[nt2 * 2 + 1][1] = q[3];
            bl[nt2 * 2][0] = p[0]; bl[nt2 * 2][1] = p[1];
            bl[nt2 * 2 + 1][0] = p[2]; bl[nt2 * 2 + 1][1] = p[3];
        }
        // A fragments per mt (keeps register count low for 2 CTAs/SM)
#pragma unroll
        for (int mt = 0; mt < 4; ++mt) {
            int row = wm * 64 + mt * 16 + (lane & 15);
            unsigned ah[4], al[4];
            LDSM4(ah, swz64(baseA, row, lane >> 4));
            LDSM4(al, swz64(baseA, row, 2 + (lane >> 4)));
#pragma unroll
            for (int nt = 0; nt < 4; ++nt) {
                MMA_OP(acc[mt][nt], ah, bh[nt]);
                MMA_OP(acc[mt][nt], ah, bl[nt]);
                MMA_OP(acc[mt][nt], al, bh[nt]);
            }
        }
    }

    // epilogue
#pragma unroll
    for (int mt = 0; mt < 4; ++mt) {
        int row0 = bm + wm * 64 + mt * 16 + (lane >> 2);
#pragma unroll
        for (int nt = 0; nt < 4; ++nt) {
            int col = bn + wn * 32 + nt * 8 + (lane & 3) * 2;
            float b0 = bias ? bias[col] : 0.f;
            float b1 = bias ? bias[col + 1] : 0.f;
            float2* p0 = (float2*)(C + (size_t)row0 * N + col);
            float2* p1 = (float2*)(C + (size_t)(row0 + 8) * N + col);
            *p0 = make_float2(acc[mt][nt][0] + b0, acc[mt][nt][1] + b1);
            *p1 = make_float2(acc[mt][nt][2] + b0, acc[mt][nt][3] + b1);
        }
    }
}

// ---------------- agent pooling: 8x8 block mean of q -> (b, 49, c) -------------
__global__ void pool_kernel(const float* __restrict__ qkv, float* __restrict__ agent)
{
    int b = blockIdx.x / AG, a = blockIdx.x % AG;
    int c = threadIdx.x;
    int py = a / 7, px = a % 7;
    float s = 0.f;
#pragma unroll
    for (int dy = 0; dy < 8; dy++) {
        int y = py * 8 + dy;
#pragma unroll
        for (int dx = 0; dx < 8; dx++) {
            int n = y * HW + px * 8 + dx;
            s += qkv[(size_t)(b * SEQ + n) * C3 + c];
        }
    }
    agent[(b * AG + a) * CDIM + c] = s * (1.f / 64.f);
}

// ---------------- bilinear 7x7 sample ------------------------------------------
__device__ __forceinline__ float bil7(const float* v, float sy, float sx)
{
    int y0 = (int)floorf(sy); float wy = sy - (float)y0;
    int x0 = (int)floorf(sx); float wx = sx - (float)x0;
    int y0c = min(max(y0, 0), 6), y1c = min(max(y0 + 1, 0), 6);
    int x0c = min(max(x0, 0), 6), x1c = min(max(x0 + 1, 0), 6);
    return (1.f - wy) * ((1.f - wx) * v[y0c * 7 + x0c] + wx * v[y0c * 7 + x1c])
         +        wy  * ((1.f - wx) * v[y1c * 7 + x0c] + wx * v[y1c * 7 + x1c]);
}

// ---------------- stage-1 bias -------------------------------------------------
__global__ void build_pb_kernel(const float* __restrict__ an,
                                const float* __restrict__ ahb,
                                const float* __restrict__ awb,
                                float* __restrict__ pb)
{
    int h = blockIdx.x, a = blockIdx.y;
    __shared__ float base[196];
    const float* v  = an  + (h * AG + a) * 49;
    const float* ah = ahb + (h * AG + a) * 14;
    const float* aw = awb + (h * AG + a) * 14;
    for (int t = threadIdx.x; t < 196; t += blockDim.x) {
        int ty = t / 14, tx = t % 14;
        base[t] = bil7(v, ty * 0.5f - 0.25f, tx * 0.5f - 0.25f) + ah[ty] + aw[tx];
    }
    __syncthreads();
    float* out = pb + (size_t)(h * AG + a) * SEQ;
    for (int j = threadIdx.x; j < SEQ; j += blockDim.x) {
        float s = ((float)j + 0.5f) * (1.f / 16.f) - 0.5f;
        int i0 = (int)floorf(s); float w = s - (float)i0;
        int i0c = min(max(i0, 0), 195), i1c = min(max(i0 + 1, 0), 195);
        out[j] = base[i0c] * (1.f - w) + base[i1c] * w;
    }
}

// ---------------- stage-2 bias -------------------------------------------------
__global__ void build_ab_kernel(const float* __restrict__ na,
                                const float* __restrict__ hab,
                                const float* __restrict__ wab,
                                const float* __restrict__ cab,
                                float* __restrict__ ab)
{
    int h = blockIdx.x, chunk = blockIdx.y;
    __shared__ float base[197 * 49];
    for (int e = threadIdx.x; e < 197 * 49; e += blockDim.x) {
        int i = e / 49, a = e % 49;
        float val;
        if (i == 0) {
            val = cab[h * AG + a];
        } else {
            int t = i - 1; int ty = t / 14, tx = t % 14;
            val = bil7(na + (h * AG + a) * 49, ty * 0.5f - 0.25f, tx * 0.5f - 0.25f)
                + hab[(h * 14 + ty) * AG + a] + wab[(h * 14 + tx) * AG + a];
        }
        base[e] = val;
    }
    __syncthreads();
    const float sc = 197.f / 3136.f;
    for (int e = threadIdx.x; e < 224 * 49; e += blockDim.x) {
        int il = e / 49, a = e % 49;
        int i = chunk * 224 + il;
        float s = ((float)i + 0.5f) * sc - 0.5f;
        int i0 = (int)floorf(s); float w = s - (float)i0;
        int i0c = min(max(i0, 0), 196), i1c = min(max(i0 + 1, 0), 196);
        ab[((size_t)h * SEQ + i) * AG + a] =
            base[i0c * 49 + a] * (1.f - w) + base[i1c * 49 + a] * w;
    }
}

// ---------------- stage-1 FUSED: flash-style agent attention -------------------
// One block per (b,h). Online softmax over j-tiles of 64. K and V share one
// smem buffer (two sub-phases). acc in registers (13 elems/thread).
__global__ __launch_bounds__(256) void s1_fused_kernel(
    const float* __restrict__ qkv, const float* __restrict__ agent,
    const float* __restrict__ pb, float* __restrict__ av)
{
    __shared__ float ahs[49 * 64];    // agent*scale (broadcast reads)
    __shared__ float kvs[64 * 65];    // K or V tile, stride 65
    __shared__ float sc[49 * 65];     // scores -> probs, stride 65
    __shared__ float m_s[49], corr_s[49], l_s[49];

    const int bh = blockIdx.x;
    const int b = bh >> 3, h = bh & 7;
    const int tid = threadIdx.x;

    for (int e = tid; e < 49 * 64; e += 256) {
        int a = e >> 6, d = e & 63;
        ahs[e] = agent[(b * AG + a) * CDIM + h * HD + d] * ASCALE;
    }
    if (tid < 49) { m_s[tid] = -1e30f; l_s[tid] = 0.f; }

    float acc[13];
#pragma unroll
    for (int k = 0; k < 13; k++) acc[k] = 0.f;

    __syncthreads();

    const float* kbase = qkv + (size_t)b * SEQ * C3 + CDIM + h * HD;
    const float* vbase = qkv + (size_t)b * SEQ * C3 + 2 * CDIM + h * HD;
    const float* pbb = pb + (size_t)(h * AG) * SEQ;

    for (int j0 = 0; j0 < SEQ; j0 += 64) {
        // load K tile
        for (int e = tid; e < 64 * 64; e += 256) {
            int r = e >> 6, d = e & 63;
            kvs[r * 65 + d] = kbase[(size_t)(j0 + r) * C3 + d];
        }
        __syncthreads();
        // scores + bias
        for (int e = tid; e < 49 * 64; e += 256) {
            int a = e >> 6, jj = e & 63;
            const float* ap = ahs + a * 64;
            const float* kp = kvs + jj * 65;
            float s = 0.f;
#pragma unroll 8
            for (int d = 0; d < 64; d++) s += ap[d] * kp[d];
            sc[a * 65 + jj] = s + pbb[(size_t)a * SEQ + j0 + jj];
        }
        __syncthreads();
        // per-agent running max
        if (tid < 49) {
            float mx = m_s[tid];
            const float* rp = sc + tid * 65;
#pragma unroll 8
            for (int jj = 0; jj < 64; jj++) mx = fmaxf(mx, rp[jj]);
            corr_s[tid] = __expf(m_s[tid] - mx);
            m_s[tid] = mx;
        }
        __syncthreads();
        // exponentiate (probs, unnormalized) + load V tile into kvs
        for (int e = tid; e < 49 * 64; e += 256) {
            int a = e >> 6, jj = e & 63;
            sc[a * 65 + jj] = __expf(sc[a * 65 + jj] - m_s[a]);
        }
        for (int e = tid; e < 64 * 64; e += 256) {
            int r = e >> 6, d = e & 63;
            kvs[r * 65 + d] = vbase[(size_t)(j0 + r) * C3 + d];
        }
        __syncthreads();
        // row-sum update + accumulate probs @ V
        if (tid < 49) {
            const float* rp = sc + tid * 65;
            float s = 0.f;
#pragma unroll 8
            for (int jj = 0; jj < 64; jj++) s += rp[jj];
            l_s[tid] = l_s[tid] * corr_s[tid] + s;
        }
#pragma unroll
        for (int k = 0; k < 13; k++) {
            int e2 = tid + k * 256;
            if (e2 < 49 * 64) {
                int a = e2 >> 6, d = e2 & 63;
                const float* pp = sc + a * 65;
                const float* vp = kvs + d;
                float s = 0.f;
#pragma unroll 8
                for (int jj = 0; jj < 64; jj++) s += pp[jj] * vp[jj * 65];
                acc[k] = acc[k] * corr_s[a] + s;
            }
        }
        __syncthreads();
    }

    // normalize and store agent_v
#pragma unroll
    for (int k = 0; k < 13; k++) {
        int e2 = tid + k * 256;
        if (e2 < 49 * 64) {
            int a = e2 >> 6, d = e2 & 63;
            av[((size_t)bh * AG + a) * HD + d] = acc[k] / l_s[a];
        }
    }
}

// ---------------- stage-2 fused ------------------------------------------------
__global__ __launch_bounds__(256) void stage2_kernel(
    const float* __restrict__ qkv, const float* __restrict__ agent,
    const float* __restrict__ av, const float* __restrict__ ab,
    float* __restrict__ tout)
{
    __shared__ float qs[32 * 64];
    __shared__ float ahs[49 * 65];
    __shared__ float avs[49 * 65];
    __shared__ float sc[32 * 56];
    int bh = blockIdx.y; int b = bh / NHEAD, h = bh % NHEAD;
    int i0 = blockIdx.x * 32;
    int tid = threadIdx.x;

    for (int e = tid; e < 49 * 64; e += 256) {
        int a = e / 64, d = e % 64;
        ahs[a * 65 + d] = agent[(b * AG + a) * CDIM + h * HD + d];
        avs[a * 65 + d] = av[((size_t)bh * AG + a) * HD + d];
    }
    for (int e = tid; e < 32 * 64; e += 256) {
        int r = e / 64, d = e % 64;
        qs[e] = qkv[(size_t)(b * SEQ + i0 + r) * C3 + h * HD + d] * ASCALE;
    }
    __syncthreads();

    for (int e = tid; e < 32 * 49; e += 256) {
        int r = e / 49, a = e % 49;
        float s = 0.f;
#pragma unroll 16
        for (int d = 0; d < 64; d++) s += qs[r * 64 + d] * ahs[a * 65 + d];
        sc[r * 56 + a] = s + ab[((size_t)h * SEQ + i0 + r) * AG + a];
    }
    __syncthreads();

    int wid = tid >> 5, lane = tid & 31;
    for (int r = wid; r < 32; r += 8) {
        float v1 = (lane < 49) ? sc[r * 56 + lane] : -1e30f;
        float v2 = (lane + 32 < 49) ? sc[r * 56 + lane + 32] : -1e30f;
        float m = fmaxf(v1, v2);
#pragma unroll
        for (int o = 16; o > 0; o >>= 1) m = fmaxf(m, __shfl_xor_sync(0xffffffffu, m, o));
        float e1 = (lane < 49) ? __expf(v1 - m) : 0.f;
        float e2 = (lane + 32 < 49) ? __expf(v2 - m) : 0.f;
        float su = e1 + e2;
#pragma unroll
        for (int o = 16; o > 0; o >>= 1) su += __shfl_xor_sync(0xffffffffu, su, o);
        float inv = 1.f / su;
        if (lane < 49) sc[r * 56 + lane] = e1 * inv;
        if (lane + 32 < 49) sc[r * 56 + lane + 32] = e2 * inv;
    }
    __syncthreads();

    for (int e = tid; e < 32 * 64; e += 256) {
        int r = e / 64, d = e % 64;
        float s = 0.f;
#pragma unroll
        for (int a = 0; a < 49; a++) s += sc[r * 56 + a] * avs[a * 65 + d];
        tout[(size_t)(b * SEQ + i0 + r) * CDIM + h * HD + d] = s;
    }
}

// ---------------- dwc 3x3 + residual + bf16 hi/lo split for proj ---------------
__global__ void dwc_split_kernel(const float* __restrict__ qkv,
                                 const float* __restrict__ wd,
                                 const float* __restrict__ bd,
                                 const float* __restrict__ tin,
                                 __nv_bfloat16* __restrict__ thi,
                                 __nv_bfloat16* __restrict__ tlo)
{
    size_t idx = (size_t)blockIdx.x * blockDim.x + threadIdx.x;
    int c = (int)(idx % CDIM);
    int n = (int)((idx / CDIM) % SEQ);
    int b = (int)(idx / ((size_t)CDIM * SEQ));
    int y = n / HW, x = n % HW;
    const float* w = wd + c * 9;
    float s = bd[c];
#pragma unroll
    for (int dy = 0; dy < 3; dy++) {
        int yy = y + dy - 1;
        if (yy < 0 || yy >= HW) continue;
#pragma unroll
        for (int dx = 0; dx < 3; dx++) {
            int xx = x + dx - 1;
            if (xx < 0 || xx >= HW) continue;
            s += w[dy * 3 + dx] * qkv[(size_t)(b * SEQ + yy * HW + xx) * C3 + 2 * CDIM + c];
        }
    }
    float val = tin[idx] + s;
    __nv_bfloat16 h = __float2bfloat16(val);
    thi[idx] = h;
    tlo[idx] = __float2bfloat16(val - __bfloat162float(h));
}

// -------------------------------------------------------------------------------
extern "C" void kernel_launch(void* const* d_in, const int* in_sizes, int n_in,
                              void* d_out, int out_size)
{
    const float* x       = (const float*)d_in[0];
    const float* w_qkv   = (const float*)d_in[1];
    const float* w_proj  = (const float*)d_in[2];
    const float* b_proj  = (const float*)d_in[3];
    const float* w_dwc   = (const float*)d_in[4];
    const float* b_dwc   = (const float*)d_in[5];
    const float* an_bias = (const float*)d_in[6];
    const float* na_bias = (const float*)d_in[7];
    const float* ah_bias = (const float*)d_in[8];
    const float* aw_bias = (const float*)d_in[9];
    const float* ha_bias = (const float*)d_in[10];
    const float* wa_bias = (const float*)d_in[11];
    const float* ca_bias = (const float*)d_in[12];

    float *qkv, *agent, *av, *pb, *ab, *t;
    __nv_bfloat16 *xhi, *xlo, *thi, *tlo, *wqhi, *wqlo, *wphi, *wplo;
    cudaGetSymbolAddress((void**)&qkv,   g_qkv);
    cudaGetSymbolAddress((void**)&agent, g_agent);
    cudaGetSymbolAddress((void**)&av,    g_av);
    cudaGetSymbolAddress((void**)&pb,    g_pb);
    cudaGetSymbolAddress((void**)&ab,    g_ab);
    cudaGetSymbolAddress((void**)&t,     g_t);
    cudaGetSymbolAddress((void**)&xhi,   g_xhi);
    cudaGetSymbolAddress((void**)&xlo,   g_xlo);
    cudaGetSymbolAddress((void**)&thi,   g_thi);
    cudaGetSymbolAddress((void**)&tlo,   g_tlo);
    cudaGetSymbolAddress((void**)&wqhi,  g_wqhi);
    cudaGetSymbolAddress((void**)&wqlo,  g_wqlo);
    cudaGetSymbolAddress((void**)&wphi,  g_wphi);
    cudaGetSymbolAddress((void**)&wplo,  g_wplo);

    const int nx4 = BATCH * SEQ * CDIM / 4;
    // 0. bf16 hi/lo splits for GEMM operands
    split_kernel<<<(nx4 + 255) / 256, 256>>>(x, xhi, xlo, nx4);
    split_kernel<<<(C3 * CDIM / 4 + 255) / 256, 256>>>(w_qkv, wqhi, wqlo, C3 * CDIM / 4);
    split_kernel<<<(CDIM * CDIM / 4 + 255) / 256, 256>>>(w_proj, wphi, wplo, CDIM * CDIM / 4);
    // 1. qkv = x @ w_qkv^T  (tensor cores, 3x bf16 split, cp.async pipeline)
    gemm_bf16x3_nt<<<dim3(C3 / 128, (BATCH * SEQ) / 128), 256>>>(
        xhi, xlo, wqhi, wqlo, qkv, nullptr, BATCH * SEQ, C3, CDIM);
    // 2. agent tokens (8x8 block mean of q)
    pool_kernel<<<BATCH * AG, CDIM>>>(qkv, agent);
    // 3. biases (batch-independent)
    build_pb_kernel<<<dim3(NHEAD, AG), 256>>>(an_bias, ah_bias, aw_bias, pb);
    build_ab_kernel<<<dim3(NHEAD, 14), 256>>>(na_bias, ha_bias, wa_bias, ca_bias, ab);
    // 4. stage-1 fused: scores + online softmax + AV in one pass over K/V
    s1_fused_kernel<<<BATCH * NHEAD, 256>>>(qkv, agent, pb, av);
    // 5. stage-2: fused q->agent attention
    stage2_kernel<<<dim3(SEQ / 32, BATCH * NHEAD), 256>>>(qkv, agent, av, ab, t);
    // 6. dwc residual + split into proj operands
    dwc_split_kernel<<<(BATCH * SEQ * CDIM) / 256, 256>>>(qkv, w_dwc, b_dwc, t, thi, tlo);
    // 7. out = t @ w_proj^T + b_proj  (tensor cores)
    gemm_bf16x3_nt<<<dim3(CDIM / 128, (BATCH * SEQ) / 128), 256>>>(
        thi, tlo, wphi, wplo, (float*)d_out, b_proj, BATCH * SEQ, CDIM, CDIM);
}

// round 12
// speedup vs baseline: 1.3146x; 1.3146x over previous
#include <cuda_runtime.h>
#include <cuda_bf16.h>
#include <math.h>

#define BATCH 16
#define SEQ   3136
#define CDIM  512
#define C3    1536
#define NHEAD 8
#define HD    64
#define AG    49
#define HW    56
#define ASCALE 0.125f

// ---------------- device-global scratch (no allocation allowed) ----------------
__device__ float g_qkv[BATCH * SEQ * C3];          // (b, n, 3c)
__device__ float g_agent[BATCH * AG * CDIM];       // (b, 49, c)
__device__ float g_av[BATCH * NHEAD * AG * HD];    // agent_v
__device__ float g_pb[NHEAD * AG * SEQ];           // stage-1 bias (upsampled)
__device__ float g_ab[NHEAD * SEQ * AG];           // stage-2 bias (upsampled)
__device__ float g_t[BATCH * SEQ * CDIM];          // attn out (pre-dwc, pre-proj)

// bf16 hi/lo split operands for tensor-core GEMMs
__device__ __nv_bfloat16 g_xhi[BATCH * SEQ * CDIM];
__device__ __nv_bfloat16 g_xlo[BATCH * SEQ * CDIM];
__device__ __nv_bfloat16 g_thi[BATCH * SEQ * CDIM];
__device__ __nv_bfloat16 g_tlo[BATCH * SEQ * CDIM];
__device__ __nv_bfloat16 g_wqhi[C3 * CDIM];
__device__ __nv_bfloat16 g_wqlo[C3 * CDIM];
__device__ __nv_bfloat16 g_wphi[CDIM * CDIM];
__device__ __nv_bfloat16 g_wplo[CDIM * CDIM];

// ---------------- fp32 -> bf16 hi/lo split (vectorized) ------------------------
__global__ void split_kernel(const float* __restrict__ in,
                             __nv_bfloat16* __restrict__ hi,
                             __nv_bfloat16* __restrict__ lo, int n4)
{
    int i = blockIdx.x * blockDim.x + threadIdx.x;
    if (i >= n4) return;
    float4 v = ((const float4*)in)[i];
    __nv_bfloat16 h0 = __float2bfloat16(v.x);
    __nv_bfloat16 h1 = __float2bfloat16(v.y);
    __nv_bfloat16 h2 = __float2bfloat16(v.z);
    __nv_bfloat16 h3 = __float2bfloat16(v.w);
    __nv_bfloat16 l0 = __float2bfloat16(v.x - __bfloat162float(h0));
    __nv_bfloat16 l1 = __float2bfloat16(v.y - __bfloat162float(h1));
    __nv_bfloat16 l2 = __float2bfloat16(v.z - __bfloat162float(h2));
    __nv_bfloat16 l3 = __float2bfloat16(v.w - __bfloat162float(h3));
    ((__nv_bfloat162*)hi)[2 * i]     = __nv_bfloat162(h0, h1);
    ((__nv_bfloat162*)hi)[2 * i + 1] = __nv_bfloat162(h2, h3);
    ((__nv_bfloat162*)lo)[2 * i]     = __nv_bfloat162(l0, l1);
    ((__nv_bfloat162*)lo)[2 * i + 1] = __nv_bfloat162(l2, l3);
}

// ---------------- tensor-core GEMM:  C[M,N] = A[M,K] * B[N,K]^T (+bias) --------
#define MMA_OP(D, A, B)                                                          \
    asm volatile("mma.sync.aligned.m16n8k16.row.col.f32.bf16.bf16.f32 "          \
                 "{%0,%1,%2,%3}, {%4,%5,%6,%7}, {%8,%9}, {%0,%1,%2,%3};\n"       \
                 : "+f"(D[0]), "+f"(D[1]), "+f"(D[2]), "+f"(D[3])                \
                 : "r"(A[0]), "r"(A[1]), "r"(A[2]), "r"(A[3]),                   \
                   "r"(B[0]), "r"(B[1]))

#define LDSM4(R, ADDR)                                                           \
    asm volatile("ldmatrix.sync.aligned.m8n8.x4.shared.b16 {%0,%1,%2,%3}, [%4];\n" \
                 : "=r"(R[0]), "=r"(R[1]), "=r"(R[2]), "=r"(R[3]) : "r"(ADDR))

#define CPA16(DST, SRC)                                                          \
    asm volatile("cp.async.ca.shared.global [%0], [%1], 16;\n"                   \
                 :: "r"(DST), "l"(SRC))

__device__ __forceinline__ unsigned swz64(unsigned base, int row, int chunk)
{
    return base + row * 64 + ((chunk ^ ((row >> 1) & 3)) << 4);
}

__global__ __launch_bounds__(256, 2) void gemm_bf16x3_nt(
    const __nv_bfloat16* __restrict__ Ahi, const __nv_bfloat16* __restrict__ Alo,
    const __nv_bfloat16* __restrict__ Bhi, const __nv_bfloat16* __restrict__ Blo,
    float* __restrict__ C, const float* __restrict__ bias,
    int M, int N, int K)
{
    __shared__ __align__(1024) unsigned char sA[3 * 128 * 64];
    __shared__ __align__(1024) unsigned char sB[3 * 128 * 64];
    const int tid = threadIdx.x;
    const int lane = tid & 31;
    const int wm = (tid >> 5) >> 2;
    const int wn = (tid >> 5) & 3;
    const int bm = blockIdx.y * 128, bn = blockIdx.x * 128;

    const unsigned sAb = (unsigned)__cvta_generic_to_shared(sA);
    const unsigned sBb = (unsigned)__cvta_generic_to_shared(sB);

    const int lr = tid >> 1;
    const int lc = tid & 1;
    const __nv_bfloat16* gAh = Ahi + (size_t)(bm + lr) * K + lc * 8;
    const __nv_bfloat16* gAl = Alo + (size_t)(bm + lr) * K + lc * 8;
    const __nv_bfloat16* gBh = Bhi + (size_t)(bn + lr) * K + lc * 8;
    const __nv_bfloat16* gBl = Blo + (size_t)(bn + lr) * K + lc * 8;
    const unsigned swzh = (unsigned)((lc       ^ ((lr >> 1) & 3)) << 4);
    const unsigned swzl = (unsigned)(((lc + 2) ^ ((lr >> 1) & 3)) << 4);

#define ISSUE_STAGE(st, k0)                                                \
    do {                                                                   \
        unsigned a0 = sAb + (st) * 8192 + lr * 64;                         \
        unsigned b0 = sBb + (st) * 8192 + lr * 64;                         \
        CPA16(a0 + swzh, gAh + (k0));                                      \
        CPA16(a0 + swzl, gAl + (k0));                                      \
        CPA16(b0 + swzh, gBh + (k0));                                      \
        CPA16(b0 + swzl, gBl + (k0));                                      \
    } while (0)

    float acc[4][4][4];
#pragma unroll
    for (int i = 0; i < 4; i++)
#pragma unroll
        for (int j = 0; j < 4; j++)
#pragma unroll
            for (int k = 0; k < 4; k++) acc[i][j][k] = 0.f;

    const int iters = K >> 4;
    ISSUE_STAGE(0, 0);
    asm volatile("cp.async.commit_group;\n" ::);
    ISSUE_STAGE(1, 16);
    asm volatile("cp.async.commit_group;\n" ::);

    for (int it = 0; it < iters; ++it) {
        asm volatile("cp.async.wait_group 1;\n" ::);
        __syncthreads();
        if (it + 2 < iters) {
            int st = (it + 2) % 3;
            int k0 = (it + 2) << 4;
            ISSUE_STAGE(st, k0);
        }
        asm volatile("cp.async.commit_group;\n" ::);

        const unsigned baseA = sAb + (it % 3) * 8192;
        const unsigned baseB = sBb + (it % 3) * 8192;

        unsigned bh[4][2], bl[4][2];
        const int m8 = lane >> 3;
#pragma unroll
        for (int nt2 = 0; nt2 < 2; ++nt2) {
            int row = wn * 32 + nt2 * 16 + (lane & 7) + ((m8 >> 1) << 3);
            unsigned q[4], p[4];
            LDSM4(q, swz64(baseB, row, m8 & 1));
            LDSM4(p, swz64(baseB, row, 2 + (m8 & 1)));
            bh[nt2 * 2][0] = q[0]; bh[nt2 * 2][1] = q[1];
            bh[nt2 * 2 + 1][0] = q[2]; bh[nt2 * 2 + 1][1] = q[3];
            bl[nt2 * 2][0] = p[0]; bl[nt2 * 2][1] = p[1];
            bl[nt2 * 2 + 1][0] = p[2]; bl[nt2 * 2 + 1][1] = p[3];
        }
#pragma unroll
        for (int mt = 0; mt < 4; ++mt) {
            int row = wm * 64 + mt * 16 + (lane & 15);
            unsigned ah[4], al[4];
            LDSM4(ah, swz64(baseA, row, lane >> 4));
            LDSM4(al, swz64(baseA, row, 2 + (lane >> 4)));
#pragma unroll
            for (int nt = 0; nt < 4; ++nt) {
                MMA_OP(acc[mt][nt], ah, bh[nt]);
                MMA_OP(acc[mt][nt], ah, bl[nt]);
                MMA_OP(acc[mt][nt], al, bh[nt]);
            }
        }
    }

#pragma unroll
    for (int mt = 0; mt < 4; ++mt) {
        int row0 = bm + wm * 64 + mt * 16 + (lane >> 2);
#pragma unroll
        for (int nt = 0; nt < 4; ++nt) {
            int col = bn + wn * 32 + nt * 8 + (lane & 3) * 2;
            float b0 = bias ? bias[col] : 0.f;
            float b1 = bias ? bias[col + 1] : 0.f;
            float2* p0 = (float2*)(C + (size_t)row0 * N + col);
            float2* p1 = (float2*)(C + (size_t)(row0 + 8) * N + col);
            *p0 = make_float2(acc[mt][nt][0] + b0, acc[mt][nt][1] + b1);
            *p1 = make_float2(acc[mt][nt][2] + b0, acc[mt][nt][3] + b1);
        }
    }
}

// ---------------- agent pooling ------------------------------------------------
__global__ void pool_kernel(const float* __restrict__ qkv, float* __restrict__ agent)
{
    int b = blockIdx.x / AG, a = blockIdx.x % AG;
    int c = threadIdx.x;
    int py = a / 7, px = a % 7;
    float s = 0.f;
#pragma unroll
    for (int dy = 0; dy < 8; dy++) {
        int y = py * 8 + dy;
#pragma unroll
        for (int dx = 0; dx < 8; dx++) {
            int n = y * HW + px * 8 + dx;
            s += qkv[(size_t)(b * SEQ + n) * C3 + c];
        }
    }
    agent[(b * AG + a) * CDIM + c] = s * (1.f / 64.f);
}

// ---------------- bilinear 7x7 sample ------------------------------------------
__device__ __forceinline__ float bil7(const float* v, float sy, float sx)
{
    int y0 = (int)floorf(sy); float wy = sy - (float)y0;
    int x0 = (int)floorf(sx); float wx = sx - (float)x0;
    int y0c = min(max(y0, 0), 6), y1c = min(max(y0 + 1, 0), 6);
    int x0c = min(max(x0, 0), 6), x1c = min(max(x0 + 1, 0), 6);
    return (1.f - wy) * ((1.f - wx) * v[y0c * 7 + x0c] + wx * v[y0c * 7 + x1c])
         +        wy  * ((1.f - wx) * v[y1c * 7 + x0c] + wx * v[y1c * 7 + x1c]);
}

// ---------------- stage-1 bias -------------------------------------------------
__global__ void build_pb_kernel(const float* __restrict__ an,
                                const float* __restrict__ ahb,
                                const float* __restrict__ awb,
                                float* __restrict__ pb)
{
    int h = blockIdx.x, a = blockIdx.y;
    __shared__ float base[196];
    const float* v  = an  + (h * AG + a) * 49;
    const float* ah = ahb + (h * AG + a) * 14;
    const float* aw = awb + (h * AG + a) * 14;
    for (int t = threadIdx.x; t < 196; t += blockDim.x) {
        int ty = t / 14, tx = t % 14;
        base[t] = bil7(v, ty * 0.5f - 0.25f, tx * 0.5f - 0.25f) + ah[ty] + aw[tx];
    }
    __syncthreads();
    float* out = pb + (size_t)(h * AG + a) * SEQ;
    for (int j = threadIdx.x; j < SEQ; j += blockDim.x) {
        float s = ((float)j + 0.5f) * (1.f / 16.f) - 0.5f;
        int i0 = (int)floorf(s); float w = s - (float)i0;
        int i0c = min(max(i0, 0), 195), i1c = min(max(i0 + 1, 0), 195);
        out[j] = base[i0c] * (1.f - w) + base[i1c] * w;
    }
}

// ---------------- stage-2 bias -------------------------------------------------
__global__ void build_ab_kernel(const float* __restrict__ na,
                                const float* __restrict__ hab,
                                const float* __restrict__ wab,
                                const float* __restrict__ cab,
                                float* __restrict__ ab)
{
    int h = blockIdx.x, chunk = blockIdx.y;
    __shared__ float base[197 * 49];
    for (int e = threadIdx.x; e < 197 * 49; e += blockDim.x) {
        int i = e / 49, a = e % 49;
        float val;
        if (i == 0) {
            val = cab[h * AG + a];
        } else {
            int t = i - 1; int ty = t / 14, tx = t % 14;
            val = bil7(na + (h * AG + a) * 49, ty * 0.5f - 0.25f, tx * 0.5f - 0.25f)
                + hab[(h * 14 + ty) * AG + a] + wab[(h * 14 + tx) * AG + a];
        }
        base[e] = val;
    }
    __syncthreads();
    const float sc = 197.f / 3136.f;
    for (int e = threadIdx.x; e < 224 * 49; e += blockDim.x) {
        int il = e / 49, a = e % 49;
        int i = chunk * 224 + il;
        float s = ((float)i + 0.5f) * sc - 0.5f;
        int i0 = (int)floorf(s); float w = s - (float)i0;
        int i0c = min(max(i0, 0), 196), i1c = min(max(i0 + 1, 0), 196);
        ab[((size_t)h * SEQ + i) * AG + a] =
            base[i0c * 49 + a] * (1.f - w) + base[i1c * 49 + a] * w;
    }
}

// ---------------- stage-1 FUSED flash-style, a-quad register tiling ------------
// One block per (b,h). 13 a-quads (a>=49 clamped to 48; duplicate rows are
// recomputed identically by the same thread — no races).
__global__ __launch_bounds__(256) void s1_fused_kernel(
    const float* __restrict__ qkv, const float* __restrict__ agent,
    const float* __restrict__ pb, float* __restrict__ av)
{
    __shared__ float ahs[49 * 64];
    __shared__ float kvs[64 * 65];
    __shared__ float sc[49 * 65];
    __shared__ float m_s[49], corr_s[49], l_s[49];

    const int bh = blockIdx.x;
    const int b = bh >> 3, h = bh & 7;
    const int tid = threadIdx.x;

    for (int e = tid; e < 49 * 64; e += 256) {
        int a = e >> 6, d = e & 63;
        ahs[e] = agent[(b * AG + a) * CDIM + h * HD + d] * ASCALE;
    }
    if (tid < 49) { m_s[tid] = -1e30f; l_s[tid] = 0.f; }

    float avacc[4][4];
#pragma unroll
    for (int s = 0; s < 4; s++)
#pragma unroll
        for (int i = 0; i < 4; i++) avacc[s][i] = 0.f;

    __syncthreads();

    const float* kbase = qkv + (size_t)b * SEQ * C3 + CDIM + h * HD;
    const float* vbase = qkv + (size_t)b * SEQ * C3 + 2 * CDIM + h * HD;
    const float* pbb = pb + (size_t)(h * AG) * SEQ;

    for (int j0 = 0; j0 < SEQ; j0 += 64) {
        // load K tile
        for (int e = tid; e < 64 * 64; e += 256) {
            int r = e >> 6, d = e & 63;
            kvs[r * 65 + d] = kbase[(size_t)(j0 + r) * C3 + d];
        }
        __syncthreads();
        // scores + bias: a-quad x jj (832 slots)
        for (int e = tid; e < 13 * 64; e += 256) {
            int aq = e >> 6, jj = e & 63;
            int a0 = aq * 4;
            int a1 = min(a0 + 1, 48), a2 = min(a0 + 2, 48), a3 = min(a0 + 3, 48);
            const float* kp = kvs + jj * 65;
            const float* p0 = ahs + a0 * 64;
            const float* p1 = ahs + a1 * 64;
            const float* p2 = ahs + a2 * 64;
            const float* p3 = ahs + a3 * 64;
            float s0 = 0.f, s1 = 0.f, s2 = 0.f, s3 = 0.f;
#pragma unroll 8
            for (int d = 0; d < 64; d++) {
                float kv = kp[d];
                s0 += p0[d] * kv; s1 += p1[d] * kv;
                s2 += p2[d] * kv; s3 += p3[d] * kv;
            }
            size_t jg = (size_t)(j0 + jj);
            sc[a0 * 65 + jj] = s0 + pbb[(size_t)a0 * SEQ + jg];
            sc[a1 * 65 + jj] = s1 + pbb[(size_t)a1 * SEQ + jg];
            sc[a2 * 65 + jj] = s2 + pbb[(size_t)a2 * SEQ + jg];
            sc[a3 * 65 + jj] = s3 + pbb[(size_t)a3 * SEQ + jg];
        }
        __syncthreads();
        // per-agent running max
        if (tid < 49) {
            float mx = m_s[tid];
            const float* rp = sc + tid * 65;
#pragma unroll 8
            for (int jj = 0; jj < 64; jj++) mx = fmaxf(mx, rp[jj]);
            corr_s[tid] = __expf(m_s[tid] - mx);
            m_s[tid] = mx;
        }
        __syncthreads();
        // exponentiate + load V tile
        for (int e = tid; e < 49 * 64; e += 256) {
            int a = e >> 6, jj = e & 63;
            sc[a * 65 + jj] = __expf(sc[a * 65 + jj] - m_s[a]);
        }
        for (int e = tid; e < 64 * 64; e += 256) {
            int r = e >> 6, d = e & 63;
            kvs[r * 65 + d] = vbase[(size_t)(j0 + r) * C3 + d];
        }
        __syncthreads();
        // row-sum update
        if (tid < 49) {
            const float* rp = sc + tid * 65;
            float s = 0.f;
#pragma unroll 8
            for (int jj = 0; jj < 64; jj++) s += rp[jj];
            l_s[tid] = l_s[tid] * corr_s[tid] + s;
        }
        // AV accumulate: a-quad x d (832 slots, persistent acc)
#pragma unroll
        for (int s = 0; s < 4; s++) {
            int e = tid + s * 256;
            if (e < 13 * 64) {
                int aq = e >> 6, d = e & 63;
                int a0 = aq * 4;
                int a1 = min(a0 + 1, 48), a2 = min(a0 + 2, 48), a3 = min(a0 + 3, 48);
                const float* vp = kvs + d;
                const float* q0 = sc + a0 * 65;
                const float* q1 = sc + a1 * 65;
                const float* q2 = sc + a2 * 65;
                const float* q3 = sc + a3 * 65;
                float t0 = 0.f, t1 = 0.f, t2 = 0.f, t3 = 0.f;
#pragma unroll 8
                for (int jj = 0; jj < 64; jj++) {
                    float vv = vp[jj * 65];
                    t0 += q0[jj] * vv; t1 += q1[jj] * vv;
                    t2 += q2[jj] * vv; t3 += q3[jj] * vv;
                }
                avacc[s][0] = avacc[s][0] * corr_s[a0] + t0;
                avacc[s][1] = avacc[s][1] * corr_s[a1] + t1;
                avacc[s][2] = avacc[s][2] * corr_s[a2] + t2;
                avacc[s][3] = avacc[s][3] * corr_s[a3] + t3;
            }
        }
        __syncthreads();
    }

    // normalize and store agent_v
#pragma unroll
    for (int s = 0; s < 4; s++) {
        int e = tid + s * 256;
        if (e < 13 * 64) {
            int aq = e >> 6, d = e & 63;
            int a0 = aq * 4;
            int a1 = min(a0 + 1, 48), a2 = min(a0 + 2, 48), a3 = min(a0 + 3, 48);
            av[((size_t)bh * AG + a0) * HD + d] = avacc[s][0] / l_s[a0];
            av[((size_t)bh * AG + a1) * HD + d] = avacc[s][1] / l_s[a1];
            av[((size_t)bh * AG + a2) * HD + d] = avacc[s][2] / l_s[a2];
            av[((size_t)bh * AG + a3) * HD + d] = avacc[s][3] / l_s[a3];
        }
    }
}

// ---------------- stage-2 fused, register-tiled --------------------------------
__global__ __launch_bounds__(256) void stage2_kernel(
    const float* __restrict__ qkv, const float* __restrict__ agent,
    const float* __restrict__ av, const float* __restrict__ ab,
    float* __restrict__ tout)
{
    __shared__ float qs[32 * 65];
    __shared__ float ahs[49 * 65];
    __shared__ float avs[49 * 65];
    __shared__ float sc[32 * 57];
    int bh = blockIdx.y; int b = bh / NHEAD, h = bh % NHEAD;
    int i0 = blockIdx.x * 32;
    int tid = threadIdx.x;

    for (int e = tid; e < 49 * 64; e += 256) {
        int a = e / 64, d = e % 64;
        ahs[a * 65 + d] = agent[(b * AG + a) * CDIM + h * HD + d];
        avs[a * 65 + d] = av[((size_t)bh * AG + a) * HD + d];
    }
    for (int e = tid; e < 32 * 64; e += 256) {
        int r = e / 64, d = e % 64;
        qs[r * 65 + d] = qkv[(size_t)(b * SEQ + i0 + r) * C3 + h * HD + d] * ASCALE;
    }
    __syncthreads();

    // scores: a-quad x r (416 slots)
    for (int e = tid; e < 13 * 32; e += 256) {
        int aq = e >> 5, r = e & 31;
        int a0 = aq * 4;
        int a1 = min(a0 + 1, 48), a2 = min(a0 + 2, 48), a3 = min(a0 + 3, 48);
        const float* qp = qs + r * 65;
        const float* p0 = ahs + a0 * 65;
        const float* p1 = ahs + a1 * 65;
        const float* p2 = ahs + a2 * 65;
        const float* p3 = ahs + a3 * 65;
        float s0 = 0.f, s1 = 0.f, s2 = 0.f, s3 = 0.f;
#pragma unroll 8
        for (int d = 0; d < 64; d++) {
            float qv = qp[d];
            s0 += p0[d] * qv; s1 += p1[d] * qv;
            s2 += p2[d] * qv; s3 += p3[d] * qv;
        }
        const float* abrow = ab + ((size_t)h * SEQ + i0 + r) * AG;
        sc[r * 57 + a0] = s0 + abrow[a0];
        sc[r * 57 + a1] = s1 + abrow[a1];
        sc[r * 57 + a2] = s2 + abrow[a2];
        sc[r * 57 + a3] = s3 + abrow[a3];
    }
    __syncthreads();

    int wid = tid >> 5, lane = tid & 31;
    for (int r = wid; r < 32; r += 8) {
        float v1 = (lane < 49) ? sc[r * 57 + lane] : -1e30f;
        float v2 = (lane + 32 < 49) ? sc[r * 57 + lane + 32] : -1e30f;
        float m = fmaxf(v1, v2);
#pragma unroll
        for (int o = 16; o > 0; o >>= 1) m = fmaxf(m, __shfl_xor_sync(0xffffffffu, m, o));
        float e1 = (lane < 49) ? __expf(v1 - m) : 0.f;
        float e2 = (lane + 32 < 49) ? __expf(v2 - m) : 0.f;
        float su = e1 + e2;
#pragma unroll
        for (int o = 16; o > 0; o >>= 1) su += __shfl_xor_sync(0xffffffffu, su, o);
        float inv = 1.f / su;
        if (lane < 49) sc[r * 57 + lane] = e1 * inv;
        if (lane + 32 < 49) sc[r * 57 + lane + 32] = e2 * inv;
    }
    __syncthreads();

    // out: r-quad x d (512 slots)
#pragma unroll
    for (int s = 0; s < 2; s++) {
        int e = tid + s * 256;
        int rq = e >> 6, d = e & 63;
        int r0 = rq * 4;
        const float* vp = avs + d;
        const float* c0 = sc + (r0 + 0) * 57;
        const float* c1 = sc + (r0 + 1) * 57;
        const float* c2 = sc + (r0 + 2) * 57;
        const float* c3 = sc + (r0 + 3) * 57;
        float t0 = 0.f, t1 = 0.f, t2 = 0.f, t3 = 0.f;
#pragma unroll
        for (int a = 0; a < 49; a++) {
            float vv = vp[a * 65];
            t0 += c0[a] * vv; t1 += c1[a] * vv;
            t2 += c2[a] * vv; t3 += c3[a] * vv;
        }
        size_t ob = (size_t)(b * SEQ + i0 + r0) * CDIM + h * HD + d;
        tout[ob]             = t0;
        tout[ob + CDIM]      = t1;
        tout[ob + 2 * CDIM]  = t2;
        tout[ob + 3 * CDIM]  = t3;
    }
}

// ---------------- dwc 3x3 + residual + bf16 hi/lo split for proj ---------------
__global__ void dwc_split_kernel(const float* __restrict__ qkv,
                                 const float* __restrict__ wd,
                                 const float* __restrict__ bd,
                                 const float* __restrict__ tin,
                                 __nv_bfloat16* __restrict__ thi,
                                 __nv_bfloat16* __restrict__ tlo)
{
    size_t idx = (size_t)blockIdx.x * blockDim.x + threadIdx.x;
    int c = (int)(idx % CDIM);
    int n = (int)((idx / CDIM) % SEQ);
    int b = (int)(idx / ((size_t)CDIM * SEQ));
    int y = n / HW, x = n % HW;
    const float* w = wd + c * 9;
    float s = bd[c];
#pragma unroll
    for (int dy = 0; dy < 3; dy++) {
        int yy = y + dy - 1;
        if (yy < 0 || yy >= HW) continue;
#pragma unroll
        for (int dx = 0; dx < 3; dx++) {
            int xx = x + dx - 1;
            if (xx < 0 || xx >= HW) continue;
            s += w[dy * 3 + dx] * qkv[(size_t)(b * SEQ + yy * HW + xx) * C3 + 2 * CDIM + c];
        }
    }
    float val = tin[idx] + s;
    __nv_bfloat16 h = __float2bfloat16(val);
    thi[idx] = h;
    tlo[idx] = __float2bfloat16(val - __bfloat162float(h));
}

// -------------------------------------------------------------------------------
extern "C" void kernel_launch(void* const* d_in, const int* in_sizes, int n_in,
                              void* d_out, int out_size)
{
    const float* x       = (const float*)d_in[0];
    const float* w_qkv   = (const float*)d_in[1];
    const float* w_proj  = (const float*)d_in[2];
    const float* b_proj  = (const float*)d_in[3];
    const float* w_dwc   = (const float*)d_in[4];
    const float* b_dwc   = (const float*)d_in[5];
    const float* an_bias = (const float*)d_in[6];
    const float* na_bias = (const float*)d_in[7];
    const float* ah_bias = (const float*)d_in[8];
    const float* aw_bias = (const float*)d_in[9];
    const float* ha_bias = (const float*)d_in[10];
    const float* wa_bias = (const float*)d_in[11];
    const float* ca_bias = (const float*)d_in[12];

    float *qkv, *agent, *av, *pb, *ab, *t;
    __nv_bfloat16 *xhi, *xlo, *thi, *tlo, *wqhi, *wqlo, *wphi, *wplo;
    cudaGetSymbolAddress((void**)&qkv,   g_qkv);
    cudaGetSymbolAddress((void**)&agent, g_agent);
    cudaGetSymbolAddress((void**)&av,    g_av);
    cudaGetSymbolAddress((void**)&pb,    g_pb);
    cudaGetSymbolAddress((void**)&ab,    g_ab);
    cudaGetSymbolAddress((void**)&t,     g_t);
    cudaGetSymbolAddress((void**)&xhi,   g_xhi);
    cudaGetSymbolAddress((void**)&xlo,   g_xlo);
    cudaGetSymbolAddress((void**)&thi,   g_thi);
    cudaGetSymbolAddress((void**)&tlo,   g_tlo);
    cudaGetSymbolAddress((void**)&wqhi,  g_wqhi);
    cudaGetSymbolAddress((void**)&wqlo,  g_wqlo);
    cudaGetSymbolAddress((void**)&wphi,  g_wphi);
    cudaGetSymbolAddress((void**)&wplo,  g_wplo);

    const int nx4 = BATCH * SEQ * CDIM / 4;
    split_kernel<<<(nx4 + 255) / 256, 256>>>(x, xhi, xlo, nx4);
    split_kernel<<<(C3 * CDIM / 4 + 255) / 256, 256>>>(w_qkv, wqhi, wqlo, C3 * CDIM / 4);
    split_kernel<<<(CDIM * CDIM / 4 + 255) / 256, 256>>>(w_proj, wphi, wplo, CDIM * CDIM / 4);
    gemm_bf16x3_nt<<<dim3(C3 / 128, (BATCH * SEQ) / 128), 256>>>(
        xhi, xlo, wqhi, wqlo, qkv, nullptr, BATCH * SEQ, C3, CDIM);
    pool_kernel<<<BATCH * AG, CDIM>>>(qkv, agent);
    build_pb_kernel<<<dim3(NHEAD, AG), 256>>>(an_bias, ah_bias, aw_bias, pb);
    build_ab_kernel<<<dim3(NHEAD, 14), 256>>>(na_bias, ha_bias, wa_bias, ca_bias, ab);
    s1_fused_kernel<<<BATCH * NHEAD, 256>>>(qkv, agent, pb, av);
    stage2_kernel<<<dim3(SEQ / 32, BATCH * NHEAD), 256>>>(qkv, agent, av, ab, t);
    dwc_split_kernel<<<(BATCH * SEQ * CDIM) / 256, 256>>>(qkv, w_dwc, b_dwc, t, thi, tlo);
    gemm_bf16x3_nt<<<dim3(CDIM / 128, (BATCH * SEQ) / 128), 256>>>(
        thi, tlo, wphi, wplo, (float*)d_out, b_proj, BATCH * SEQ, CDIM, CDIM);
}

// round 13
// speedup vs baseline: 1.3993x; 1.0645x over previous
#include <cuda_runtime.h>
#include <cuda_bf16.h>
#include <math.h>

#define BATCH 16
#define SEQ   3136
#define CDIM  512
#define C3    1536
#define NHEAD 8
#define HD    64
#define AG    49
#define HW    56
#define ASCALE 0.125f
#define S1CH  4          // split-K chunks for stage-1

// ---------------- device-global scratch (no allocation allowed) ----------------
__device__ float g_qkv[BATCH * SEQ * C3];          // (b, n, 3c)
__device__ float g_agent[BATCH * AG * CDIM];       // (b, 49, c)
__device__ float g_av[BATCH * NHEAD * AG * HD];    // agent_v
__device__ float g_pb[NHEAD * AG * SEQ];           // stage-1 bias (upsampled)
__device__ float g_ab[NHEAD * SEQ * AG];           // stage-2 bias (upsampled)
// stage-1 split-K partials
__device__ float g_pm[BATCH * NHEAD * S1CH * AG];
__device__ float g_pl[BATCH * NHEAD * S1CH * AG];
__device__ float g_pacc[BATCH * NHEAD * S1CH * AG * HD];

// bf16 hi/lo split operands for tensor-core GEMMs
__device__ __nv_bfloat16 g_xhi[BATCH * SEQ * CDIM];
__device__ __nv_bfloat16 g_xlo[BATCH * SEQ * CDIM];
__device__ __nv_bfloat16 g_thi[BATCH * SEQ * CDIM];
__device__ __nv_bfloat16 g_tlo[BATCH * SEQ * CDIM];
__device__ __nv_bfloat16 g_wqhi[C3 * CDIM];
__device__ __nv_bfloat16 g_wqlo[C3 * CDIM];
__device__ __nv_bfloat16 g_wphi[CDIM * CDIM];
__device__ __nv_bfloat16 g_wplo[CDIM * CDIM];

// ---------------- fp32 -> bf16 hi/lo split (vectorized) ------------------------
__global__ void split_kernel(const float* __restrict__ in,
                             __nv_bfloat16* __restrict__ hi,
                             __nv_bfloat16* __restrict__ lo, int n4)
{
    int i = blockIdx.x * blockDim.x + threadIdx.x;
    if (i >= n4) return;
    float4 v = ((const float4*)in)[i];
    __nv_bfloat16 h0 = __float2bfloat16(v.x);
    __nv_bfloat16 h1 = __float2bfloat16(v.y);
    __nv_bfloat16 h2 = __float2bfloat16(v.z);
    __nv_bfloat16 h3 = __float2bfloat16(v.w);
    __nv_bfloat16 l0 = __float2bfloat16(v.x - __bfloat162float(h0));
    __nv_bfloat16 l1 = __float2bfloat16(v.y - __bfloat162float(h1));
    __nv_bfloat16 l2 = __float2bfloat16(v.z - __bfloat162float(h2));
    __nv_bfloat16 l3 = __float2bfloat16(v.w - __bfloat162float(h3));
    ((__nv_bfloat162*)hi)[2 * i]     = __nv_bfloat162(h0, h1);
    ((__nv_bfloat162*)hi)[2 * i + 1] = __nv_bfloat162(h2, h3);
    ((__nv_bfloat162*)lo)[2 * i]     = __nv_bfloat162(l0, l1);
    ((__nv_bfloat162*)lo)[2 * i + 1] = __nv_bfloat162(l2, l3);
}

// ---------------- tensor-core GEMM:  C[M,N] = A[M,K] * B[N,K]^T (+bias) --------
#define MMA_OP(D, A, B)                                                          \
    asm volatile("mma.sync.aligned.m16n8k16.row.col.f32.bf16.bf16.f32 "          \
                 "{%0,%1,%2,%3}, {%4,%5,%6,%7}, {%8,%9}, {%0,%1,%2,%3};\n"       \
                 : "+f"(D[0]), "+f"(D[1]), "+f"(D[2]), "+f"(D[3])                \
                 : "r"(A[0]), "r"(A[1]), "r"(A[2]), "r"(A[3]),                   \
                   "r"(B[0]), "r"(B[1]))

#define LDSM4(R, ADDR)                                                           \
    asm volatile("ldmatrix.sync.aligned.m8n8.x4.shared.b16 {%0,%1,%2,%3}, [%4];\n" \
                 : "=r"(R[0]), "=r"(R[1]), "=r"(R[2]), "=r"(R[3]) : "r"(ADDR))

#define CPA16(DST, SRC)                                                          \
    asm volatile("cp.async.ca.shared.global [%0], [%1], 16;\n"                   \
                 :: "r"(DST), "l"(SRC))

__device__ __forceinline__ unsigned swz64(unsigned base, int row, int chunk)
{
    return base + row * 64 + ((chunk ^ ((row >> 1) & 3)) << 4);
}

__global__ __launch_bounds__(256, 2) void gemm_bf16x3_nt(
    const __nv_bfloat16* __restrict__ Ahi, const __nv_bfloat16* __restrict__ Alo,
    const __nv_bfloat16* __restrict__ Bhi, const __nv_bfloat16* __restrict__ Blo,
    float* __restrict__ C, const float* __restrict__ bias,
    int M, int N, int K)
{
    __shared__ __align__(1024) unsigned char sA[3 * 128 * 64];
    __shared__ __align__(1024) unsigned char sB[3 * 128 * 64];
    const int tid = threadIdx.x;
    const int lane = tid & 31;
    const int wm = (tid >> 5) >> 2;
    const int wn = (tid >> 5) & 3;
    const int bm = blockIdx.y * 128, bn = blockIdx.x * 128;

    const unsigned sAb = (unsigned)__cvta_generic_to_shared(sA);
    const unsigned sBb = (unsigned)__cvta_generic_to_shared(sB);

    const int lr = tid >> 1;
    const int lc = tid & 1;
    const __nv_bfloat16* gAh = Ahi + (size_t)(bm + lr) * K + lc * 8;
    const __nv_bfloat16* gAl = Alo + (size_t)(bm + lr) * K + lc * 8;
    const __nv_bfloat16* gBh = Bhi + (size_t)(bn + lr) * K + lc * 8;
    const __nv_bfloat16* gBl = Blo + (size_t)(bn + lr) * K + lc * 8;
    const unsigned swzh = (unsigned)((lc       ^ ((lr >> 1) & 3)) << 4);
    const unsigned swzl = (unsigned)(((lc + 2) ^ ((lr >> 1) & 3)) << 4);

#define ISSUE_STAGE(st, k0)                                                \
    do {                                                                   \
        unsigned a0 = sAb + (st) * 8192 + lr * 64;                         \
        unsigned b0 = sBb + (st) * 8192 + lr * 64;                         \
        CPA16(a0 + swzh, gAh + (k0));                                      \
        CPA16(a0 + swzl, gAl + (k0));                                      \
        CPA16(b0 + swzh, gBh + (k0));                                      \
        CPA16(b0 + swzl, gBl + (k0));                                      \
    } while (0)

    float acc[4][4][4];
#pragma unroll
    for (int i = 0; i < 4; i++)
#pragma unroll
        for (int j = 0; j < 4; j++)
#pragma unroll
            for (int k = 0; k < 4; k++) acc[i][j][k] = 0.f;

    const int iters = K >> 4;
    ISSUE_STAGE(0, 0);
    asm volatile("cp.async.commit_group;\n" ::);
    ISSUE_STAGE(1, 16);
    asm volatile("cp.async.commit_group;\n" ::);

    for (int it = 0; it < iters; ++it) {
        asm volatile("cp.async.wait_group 1;\n" ::);
        __syncthreads();
        if (it + 2 < iters) {
            int st = (it + 2) % 3;
            int k0 = (it + 2) << 4;
            ISSUE_STAGE(st, k0);
        }
        asm volatile("cp.async.commit_group;\n" ::);

        const unsigned baseA = sAb + (it % 3) * 8192;
        const unsigned baseB = sBb + (it % 3) * 8192;

        unsigned bh[4][2], bl[4][2];
        const int m8 = lane >> 3;
#pragma unroll
        for (int nt2 = 0; nt2 < 2; ++nt2) {
            int row = wn * 32 + nt2 * 16 + (lane & 7) + ((m8 >> 1) << 3);
            unsigned q[4], p[4];
            LDSM4(q, swz64(baseB, row, m8 & 1));
            LDSM4(p, swz64(baseB, row, 2 + (m8 & 1)));
            bh[nt2 * 2][0] = q[0]; bh[nt2 * 2][1] = q[1];
            bh[nt2 * 2 + 1][0] = q[2]; bh[nt2 * 2 + 1][1] = q[3];
            bl[nt2 * 2][0] = p[0]; bl[nt2 * 2][1] = p[1];
            bl[nt2 * 2 + 1][0] = p[2]; bl[nt2 * 2 + 1][1] = p[3];
        }
#pragma unroll
        for (int mt = 0; mt < 4; ++mt) {
            int row = wm * 64 + mt * 16 + (lane & 15);
            unsigned ah[4], al[4];
            LDSM4(ah, swz64(baseA, row, lane >> 4));
            LDSM4(al, swz64(baseA, row, 2 + (lane >> 4)));
#pragma unroll
            for (int nt = 0; nt < 4; ++nt) {
                MMA_OP(acc[mt][nt], ah, bh[nt]);
                MMA_OP(acc[mt][nt], ah, bl[nt]);
                MMA_OP(acc[mt][nt], al, bh[nt]);
            }
        }
    }

#pragma unroll
    for (int mt = 0; mt < 4; ++mt) {
        int row0 = bm + wm * 64 + mt * 16 + (lane >> 2);
#pragma unroll
        for (int nt = 0; nt < 4; ++nt) {
            int col = bn + wn * 32 + nt * 8 + (lane & 3) * 2;
            float b0 = bias ? bias[col] : 0.f;
            float b1 = bias ? bias[col + 1] : 0.f;
            float2* p0 = (float2*)(C + (size_t)row0 * N + col);
            float2* p1 = (float2*)(C + (size_t)(row0 + 8) * N + col);
            *p0 = make_float2(acc[mt][nt][0] + b0, acc[mt][nt][1] + b1);
            *p1 = make_float2(acc[mt][nt][2] + b0, acc[mt][nt][3] + b1);
        }
    }
}

// ---------------- agent pooling ------------------------------------------------
__global__ void pool_kernel(const float* __restrict__ qkv, float* __restrict__ agent)
{
    int b = blockIdx.x / AG, a = blockIdx.x % AG;
    int c = threadIdx.x;
    int py = a / 7, px = a % 7;
    float s = 0.f;
#pragma unroll
    for (int dy = 0; dy < 8; dy++) {
        int y = py * 8 + dy;
#pragma unroll
        for (int dx = 0; dx < 8; dx++) {
            int n = y * HW + px * 8 + dx;
            s += qkv[(size_t)(b * SEQ + n) * C3 + c];
        }
    }
    agent[(b * AG + a) * CDIM + c] = s * (1.f / 64.f);
}

// ---------------- bilinear 7x7 sample ------------------------------------------
__device__ __forceinline__ float bil7(const float* v, float sy, float sx)
{
    int y0 = (int)floorf(sy); float wy = sy - (float)y0;
    int x0 = (int)floorf(sx); float wx = sx - (float)x0;
    int y0c = min(max(y0, 0), 6), y1c = min(max(y0 + 1, 0), 6);
    int x0c = min(max(x0, 0), 6), x1c = min(max(x0 + 1, 0), 6);
    return (1.f - wy) * ((1.f - wx) * v[y0c * 7 + x0c] + wx * v[y0c * 7 + x1c])
         +        wy  * ((1.f - wx) * v[y1c * 7 + x0c] + wx * v[y1c * 7 + x1c]);
}

// ---------------- stage-1 bias -------------------------------------------------
__global__ void build_pb_kernel(const float* __restrict__ an,
                                const float* __restrict__ ahb,
                                const float* __restrict__ awb,
                                float* __restrict__ pb)
{
    int h = blockIdx.x, a = blockIdx.y;
    __shared__ float base[196];
    const float* v  = an  + (h * AG + a) * 49;
    const float* ah = ahb + (h * AG + a) * 14;
    const float* aw = awb + (h * AG + a) * 14;
    for (int t = threadIdx.x; t < 196; t += blockDim.x) {
        int ty = t / 14, tx = t % 14;
        base[t] = bil7(v, ty * 0.5f - 0.25f, tx * 0.5f - 0.25f) + ah[ty] + aw[tx];
    }
    __syncthreads();
    float* out = pb + (size_t)(h * AG + a) * SEQ;
    for (int j = threadIdx.x; j < SEQ; j += blockDim.x) {
        float s = ((float)j + 0.5f) * (1.f / 16.f) - 0.5f;
        int i0 = (int)floorf(s); float w = s - (float)i0;
        int i0c = min(max(i0, 0), 195), i1c = min(max(i0 + 1, 0), 195);
        out[j] = base[i0c] * (1.f - w) + base[i1c] * w;
    }
}

// ---------------- stage-2 bias -------------------------------------------------
__global__ void build_ab_kernel(const float* __restrict__ na,
                                const float* __restrict__ hab,
                                const float* __restrict__ wab,
                                const float* __restrict__ cab,
                                float* __restrict__ ab)
{
    int h = blockIdx.x, chunk = blockIdx.y;
    __shared__ float base[197 * 49];
    for (int e = threadIdx.x; e < 197 * 49; e += blockDim.x) {
        int i = e / 49, a = e % 49;
        float val;
        if (i == 0) {
            val = cab[h * AG + a];
        } else {
            int t = i - 1; int ty = t / 14, tx = t % 14;
            val = bil7(na + (h * AG + a) * 49, ty * 0.5f - 0.25f, tx * 0.5f - 0.25f)
                + hab[(h * 14 + ty) * AG + a] + wab[(h * 14 + tx) * AG + a];
        }
        base[e] = val;
    }
    __syncthreads();
    const float sc = 197.f / 3136.f;
    for (int e = threadIdx.x; e < 224 * 49; e += blockDim.x) {
        int il = e / 49, a = e % 49;
        int i = chunk * 224 + il;
        float s = ((float)i + 0.5f) * sc - 0.5f;
        int i0 = (int)floorf(s); float w = s - (float)i0;
        int i0c = min(max(i0, 0), 196), i1c = min(max(i0 + 1, 0), 196);
        ab[((size_t)h * SEQ + i) * AG + a] =
            base[i0c * 49 + a] * (1.f - w) + base[i1c * 49 + a] * w;
    }
}

// ---------------- stage-1 split-K partial: flash over a j-chunk ----------------
// grid (S1CH, BATCH*NHEAD). 49 j-tiles of 64 split as 12/12/12/13.
__global__ __launch_bounds__(256) void s1_part_kernel(
    const float* __restrict__ qkv, const float* __restrict__ agent,
    const float* __restrict__ pb,
    float* __restrict__ pm, float* __restrict__ pl, float* __restrict__ pacc)
{
    __shared__ float ahs[49 * 64];
    __shared__ float kvs[64 * 65];
    __shared__ float sc[49 * 65];
    __shared__ float m_s[49], corr_s[49], l_s[49];

    const int chunk = blockIdx.x;
    const int bh = blockIdx.y;
    const int b = bh >> 3, h = bh & 7;
    const int tid = threadIdx.x;
    const int tbeg = chunk * 12;
    const int tend = (chunk == S1CH - 1) ? 49 : tbeg + 12;

    for (int e = tid; e < 49 * 64; e += 256) {
        int a = e >> 6, d = e & 63;
        ahs[e] = agent[(b * AG + a) * CDIM + h * HD + d] * ASCALE;
    }
    if (tid < 49) { m_s[tid] = -1e30f; l_s[tid] = 0.f; }

    float avacc[4][4];
#pragma unroll
    for (int s = 0; s < 4; s++)
#pragma unroll
        for (int i = 0; i < 4; i++) avacc[s][i] = 0.f;

    __syncthreads();

    const float* kbase = qkv + (size_t)b * SEQ * C3 + CDIM + h * HD;
    const float* vbase = qkv + (size_t)b * SEQ * C3 + 2 * CDIM + h * HD;
    const float* pbb = pb + (size_t)(h * AG) * SEQ;

    for (int t = tbeg; t < tend; ++t) {
        const int j0 = t * 64;
        for (int e = tid; e < 64 * 64; e += 256) {
            int r = e >> 6, d = e & 63;
            kvs[r * 65 + d] = kbase[(size_t)(j0 + r) * C3 + d];
        }
        __syncthreads();
        for (int e = tid; e < 13 * 64; e += 256) {
            int aq = e >> 6, jj = e & 63;
            int a0 = aq * 4;
            int a1 = min(a0 + 1, 48), a2 = min(a0 + 2, 48), a3 = min(a0 + 3, 48);
            const float* kp = kvs + jj * 65;
            const float* p0 = ahs + a0 * 64;
            const float* p1 = ahs + a1 * 64;
            const float* p2 = ahs + a2 * 64;
            const float* p3 = ahs + a3 * 64;
            float s0 = 0.f, s1 = 0.f, s2 = 0.f, s3 = 0.f;
#pragma unroll 8
            for (int d = 0; d < 64; d++) {
                float kv = kp[d];
                s0 += p0[d] * kv; s1 += p1[d] * kv;
                s2 += p2[d] * kv; s3 += p3[d] * kv;
            }
            size_t jg = (size_t)(j0 + jj);
            sc[a0 * 65 + jj] = s0 + pbb[(size_t)a0 * SEQ + jg];
            sc[a1 * 65 + jj] = s1 + pbb[(size_t)a1 * SEQ + jg];
            sc[a2 * 65 + jj] = s2 + pbb[(size_t)a2 * SEQ + jg];
            sc[a3 * 65 + jj] = s3 + pbb[(size_t)a3 * SEQ + jg];
        }
        __syncthreads();
        if (tid < 49) {
            float mx = m_s[tid];
            const float* rp = sc + tid * 65;
#pragma unroll 8
            for (int jj = 0; jj < 64; jj++) mx = fmaxf(mx, rp[jj]);
            corr_s[tid] = __expf(m_s[tid] - mx);
            m_s[tid] = mx;
        }
        __syncthreads();
        for (int e = tid; e < 49 * 64; e += 256) {
            int a = e >> 6, jj = e & 63;
            sc[a * 65 + jj] = __expf(sc[a * 65 + jj] - m_s[a]);
        }
        for (int e = tid; e < 64 * 64; e += 256) {
            int r = e >> 6, d = e & 63;
            kvs[r * 65 + d] = vbase[(size_t)(j0 + r) * C3 + d];
        }
        __syncthreads();
        if (tid < 49) {
            const float* rp = sc + tid * 65;
            float s = 0.f;
#pragma unroll 8
            for (int jj = 0; jj < 64; jj++) s += rp[jj];
            l_s[tid] = l_s[tid] * corr_s[tid] + s;
        }
#pragma unroll
        for (int s = 0; s < 4; s++) {
            int e = tid + s * 256;
            if (e < 13 * 64) {
                int aq = e >> 6, d = e & 63;
                int a0 = aq * 4;
                int a1 = min(a0 + 1, 48), a2 = min(a0 + 2, 48), a3 = min(a0 + 3, 48);
                const float* vp = kvs + d;
                const float* q0 = sc + a0 * 65;
                const float* q1 = sc + a1 * 65;
                const float* q2 = sc + a2 * 65;
                const float* q3 = sc + a3 * 65;
                float t0 = 0.f, t1 = 0.f, t2 = 0.f, t3 = 0.f;
#pragma unroll 8
                for (int jj = 0; jj < 64; jj++) {
                    float vv = vp[jj * 65];
                    t0 += q0[jj] * vv; t1 += q1[jj] * vv;
                    t2 += q2[jj] * vv; t3 += q3[jj] * vv;
                }
                avacc[s][0] = avacc[s][0] * corr_s[a0] + t0;
                avacc[s][1] = avacc[s][1] * corr_s[a1] + t1;
                avacc[s][2] = avacc[s][2] * corr_s[a2] + t2;
                avacc[s][3] = avacc[s][3] * corr_s[a3] + t3;
            }
        }
        __syncthreads();
    }

    // store partials (unnormalized)
    const int pidx = bh * S1CH + chunk;
    if (tid < 49) {
        pm[pidx * AG + tid] = m_s[tid];
        pl[pidx * AG + tid] = l_s[tid];
    }
#pragma unroll
    for (int s = 0; s < 4; s++) {
        int e = tid + s * 256;
        if (e < 13 * 64) {
            int aq = e >> 6, d = e & 63;
            int a0 = aq * 4;
            int a1 = min(a0 + 1, 48), a2 = min(a0 + 2, 48), a3 = min(a0 + 3, 48);
            pacc[((size_t)pidx * AG + a0) * HD + d] = avacc[s][0];
            pacc[((size_t)pidx * AG + a1) * HD + d] = avacc[s][1];
            pacc[((size_t)pidx * AG + a2) * HD + d] = avacc[s][2];
            pacc[((size_t)pidx * AG + a3) * HD + d] = avacc[s][3];
        }
    }
}

// ---------------- stage-1 combine: merge split-K partials ----------------------
__global__ void s1_combine_kernel(const float* __restrict__ pm,
                                  const float* __restrict__ pl,
                                  const float* __restrict__ pacc,
                                  float* __restrict__ av)
{
    const int bh = blockIdx.x;
    const int tid = threadIdx.x;
    for (int e = tid; e < AG * HD; e += 256) {
        int a = e >> 6, d = e & 63;
        float m0 = pm[(bh * S1CH + 0) * AG + a];
        float m1 = pm[(bh * S1CH + 1) * AG + a];
        float m2 = pm[(bh * S1CH + 2) * AG + a];
        float m3 = pm[(bh * S1CH + 3) * AG + a];
        float M = fmaxf(fmaxf(m0, m1), fmaxf(m2, m3));
        float w0 = __expf(m0 - M), w1 = __expf(m1 - M);
        float w2 = __expf(m2 - M), w3 = __expf(m3 - M);
        float num = pacc[((size_t)(bh * S1CH + 0) * AG + a) * HD + d] * w0
                  + pacc[((size_t)(bh * S1CH + 1) * AG + a) * HD + d] * w1
                  + pacc[((size_t)(bh * S1CH + 2) * AG + a) * HD + d] * w2
                  + pacc[((size_t)(bh * S1CH + 3) * AG + a) * HD + d] * w3;
        float den = pl[(bh * S1CH + 0) * AG + a] * w0
                  + pl[(bh * S1CH + 1) * AG + a] * w1
                  + pl[(bh * S1CH + 2) * AG + a] * w2
                  + pl[(bh * S1CH + 3) * AG + a] * w3;
        av[((size_t)bh * AG + a) * HD + d] = num / den;
    }
}

// ---------------- stage-2 fused + dwc + bf16 split epilogue --------------------
__global__ __launch_bounds__(256) void stage2_kernel(
    const float* __restrict__ qkv, const float* __restrict__ agent,
    const float* __restrict__ av, const float* __restrict__ ab,
    const float* __restrict__ wd, const float* __restrict__ bd,
    __nv_bfloat16* __restrict__ thi, __nv_bfloat16* __restrict__ tlo)
{
    __shared__ float qs[32 * 65];
    __shared__ float ahs[49 * 65];
    __shared__ float avs[49 * 65];
    __shared__ float sc[32 * 57];
    int bh = blockIdx.y; int b = bh / NHEAD, h = bh % NHEAD;
    int i0 = blockIdx.x * 32;
    int tid = threadIdx.x;

    for (int e = tid; e < 49 * 64; e += 256) {
        int a = e / 64, d = e % 64;
        ahs[a * 65 + d] = agent[(b * AG + a) * CDIM + h * HD + d];
        avs[a * 65 + d] = av[((size_t)bh * AG + a) * HD + d];
    }
    for (int e = tid; e < 32 * 64; e += 256) {
        int r = e / 64, d = e % 64;
        qs[r * 65 + d] = qkv[(size_t)(b * SEQ + i0 + r) * C3 + h * HD + d] * ASCALE;
    }
    __syncthreads();

    for (int e = tid; e < 13 * 32; e += 256) {
        int aq = e >> 5, r = e & 31;
        int a0 = aq * 4;
        int a1 = min(a0 + 1, 48), a2 = min(a0 + 2, 48), a3 = min(a0 + 3, 48);
        const float* qp = qs + r * 65;
        const float* p0 = ahs + a0 * 65;
        const float* p1 = ahs + a1 * 65;
        const float* p2 = ahs + a2 * 65;
        const float* p3 = ahs + a3 * 65;
        float s0 = 0.f, s1 = 0.f, s2 = 0.f, s3 = 0.f;
#pragma unroll 8
        for (int d = 0; d < 64; d++) {
            float qv = qp[d];
            s0 += p0[d] * qv; s1 += p1[d] * qv;
            s2 += p2[d] * qv; s3 += p3[d] * qv;
        }
        const float* abrow = ab + ((size_t)h * SEQ + i0 + r) * AG;
        sc[r * 57 + a0] = s0 + abrow[a0];
        sc[r * 57 + a1] = s1 + abrow[a1];
        sc[r * 57 + a2] = s2 + abrow[a2];
        sc[r * 57 + a3] = s3 + abrow[a3];
    }
    __syncthreads();

    int wid = tid >> 5, lane = tid & 31;
    for (int r = wid; r < 32; r += 8) {
        float v1 = (lane < 49) ? sc[r * 57 + lane] : -1e30f;
        float v2 = (lane + 32 < 49) ? sc[r * 57 + lane + 32] : -1e30f;
        float m = fmaxf(v1, v2);
#pragma unroll
        for (int o = 16; o > 0; o >>= 1) m = fmaxf(m, __shfl_xor_sync(0xffffffffu, m, o));
        float e1 = (lane < 49) ? __expf(v1 - m) : 0.f;
        float e2 = (lane + 32 < 49) ? __expf(v2 - m) : 0.f;
        float su = e1 + e2;
#pragma unroll
        for (int o = 16; o > 0; o >>= 1) su += __shfl_xor_sync(0xffffffffu, su, o);
        float inv = 1.f / su;
        if (lane < 49) sc[r * 57 + lane] = e1 * inv;
        if (lane + 32 < 49) sc[r * 57 + lane + 32] = e2 * inv;
    }
    __syncthreads();

    // out: r-quad x d, then + dwc(v) + bias, split to bf16 hi/lo
    const int c = h * HD;      // head channel base
    const float* vpart = qkv + (size_t)b * SEQ * C3 + 2 * CDIM;
#pragma unroll
    for (int s = 0; s < 2; s++) {
        int e = tid + s * 256;
        int rq = e >> 6, d = e & 63;
        int r0 = rq * 4;
        const float* vp = avs + d;
        const float* c0 = sc + (r0 + 0) * 57;
        const float* c1 = sc + (r0 + 1) * 57;
        const float* c2 = sc + (r0 + 2) * 57;
        const float* c3 = sc + (r0 + 3) * 57;
        float t0 = 0.f, t1 = 0.f, t2 = 0.f, t3 = 0.f;
#pragma unroll
        for (int a = 0; a < 49; a++) {
            float vv = vp[a * 65];
            t0 += c0[a] * vv; t1 += c1[a] * vv;
            t2 += c2[a] * vv; t3 += c3[a] * vv;
        }
        float res[4] = {t0, t1, t2, t3};
        const int cc = c + d;
        const float* w = wd + cc * 9;
        float w00 = w[0], w01 = w[1], w02 = w[2];
        float w10 = w[3], w11 = w[4], w12 = w[5];
        float w20 = w[6], w21 = w[7], w22 = w[8];
        float bias_c = bd[cc];
#pragma unroll
        for (int i = 0; i < 4; i++) {
            int n = i0 + r0 + i;
            int y = n / HW, x = n % HW;
            float sconv = bias_c;
#pragma unroll
            for (int dy = 0; dy < 3; dy++) {
                int yy = y + dy - 1;
                if (yy < 0 || yy >= HW) continue;
                float wr0 = (dy == 0) ? w00 : (dy == 1) ? w10 : w20;
                float wr1 = (dy == 0) ? w01 : (dy == 1) ? w11 : w21;
                float wr2 = (dy == 0) ? w02 : (dy == 1) ? w12 : w22;
                const float* vrow = vpart + (size_t)(yy * HW) * C3 + cc;
                if (x - 1 >= 0)  sconv += wr0 * vrow[(size_t)(x - 1) * C3];
                sconv += wr1 * vrow[(size_t)x * C3];
                if (x + 1 < HW)  sconv += wr2 * vrow[(size_t)(x + 1) * C3];
            }
            float val = res[i] + sconv;
            __nv_bfloat16 hh = __float2bfloat16(val);
            size_t ob = (size_t)(b * SEQ + n) * CDIM + cc;
            thi[ob] = hh;
            tlo[ob] = __float2bfloat16(val - __bfloat162float(hh));
        }
    }
}

// -------------------------------------------------------------------------------
extern "C" void kernel_launch(void* const* d_in, const int* in_sizes, int n_in,
                              void* d_out, int out_size)
{
    const float* x       = (const float*)d_in[0];
    const float* w_qkv   = (const float*)d_in[1];
    const float* w_proj  = (const float*)d_in[2];
    const float* b_proj  = (const float*)d_in[3];
    const float* w_dwc   = (const float*)d_in[4];
    const float* b_dwc   = (const float*)d_in[5];
    const float* an_bias = (const float*)d_in[6];
    const float* na_bias = (const float*)d_in[7];
    const float* ah_bias = (const float*)d_in[8];
    const float* aw_bias = (const float*)d_in[9];
    const float* ha_bias = (const float*)d_in[10];
    const float* wa_bias = (const float*)d_in[11];
    const float* ca_bias = (const float*)d_in[12];

    float *qkv, *agent, *av, *pb, *ab, *pm, *pl, *pacc;
    __nv_bfloat16 *xhi, *xlo, *thi, *tlo, *wqhi, *wqlo, *wphi, *wplo;
    cudaGetSymbolAddress((void**)&qkv,   g_qkv);
    cudaGetSymbolAddress((void**)&agent, g_agent);
    cudaGetSymbolAddress((void**)&av,    g_av);
    cudaGetSymbolAddress((void**)&pb,    g_pb);
    cudaGetSymbolAddress((void**)&ab,    g_ab);
    cudaGetSymbolAddress((void**)&pm,    g_pm);
    cudaGetSymbolAddress((void**)&pl,    g_pl);
    cudaGetSymbolAddress((void**)&pacc,  g_pacc);
    cudaGetSymbolAddress((void**)&xhi,   g_xhi);
    cudaGetSymbolAddress((void**)&xlo,   g_xlo);
    cudaGetSymbolAddress((void**)&thi,   g_thi);
    cudaGetSymbolAddress((void**)&tlo,   g_tlo);
    cudaGetSymbolAddress((void**)&wqhi,  g_wqhi);
    cudaGetSymbolAddress((void**)&wqlo,  g_wqlo);
    cudaGetSymbolAddress((void**)&wphi,  g_wphi);
    cudaGetSymbolAddress((void**)&wplo,  g_wplo);

    const int nx4 = BATCH * SEQ * CDIM / 4;
    split_kernel<<<(nx4 + 255) / 256, 256>>>(x, xhi, xlo, nx4);
    split_kernel<<<(C3 * CDIM / 4 + 255) / 256, 256>>>(w_qkv, wqhi, wqlo, C3 * CDIM / 4);
    split_kernel<<<(CDIM * CDIM / 4 + 255) / 256, 256>>>(w_proj, wphi, wplo, CDIM * CDIM / 4);
    gemm_bf16x3_nt<<<dim3(C3 / 128, (BATCH * SEQ) / 128), 256>>>(
        xhi, xlo, wqhi, wqlo, qkv, nullptr, BATCH * SEQ, C3, CDIM);
    pool_kernel<<<BATCH * AG, CDIM>>>(qkv, agent);
    build_pb_kernel<<<dim3(NHEAD, AG), 256>>>(an_bias, ah_bias, aw_bias, pb);
    build_ab_kernel<<<dim3(NHEAD, 14), 256>>>(na_bias, ha_bias, wa_bias, ca_bias, ab);
    // stage-1 split-K flash + combine
    s1_part_kernel<<<dim3(S1CH, BATCH * NHEAD), 256>>>(qkv, agent, pb, pm, pl, pacc);
    s1_combine_kernel<<<BATCH * NHEAD, 256>>>(pm, pl, pacc, av);
    // stage-2 + dwc + bf16 split epilogue (writes proj operands directly)
    stage2_kernel<<<dim3(SEQ / 32, BATCH * NHEAD), 256>>>(
        qkv, agent, av, ab, w_dwc, b_dwc, thi, tlo);
    gemm_bf16x3_nt<<<dim3(CDIM / 128, (BATCH * SEQ) / 128), 256>>>(
        thi, tlo, wphi, wplo, (float*)d_out, b_proj, BATCH * SEQ, CDIM, CDIM);
}